// round 7
// baseline (speedup 1.0000x reference)
#include <cuda_runtime.h>
#include <cstdint>

#define HG_L 16
#define HG_T (1u << 19)
#define HG_TMASK (HG_T - 1u)
#define WIDTH 64

#define P1 2654435761u
#define P2 805459861u
#define P3 3674653429u

typedef unsigned long long u64;

// floor(16 * 1.5^l) for l = 0..15
__constant__ float c_res[HG_L] = {
    16.f, 24.f, 36.f, 54.f, 81.f, 121.f, 182.f, 273.f,
    410.f, 615.f, 922.f, 1383.f, 2075.f, 3113.f, 4670.f, 7006.f
};

// All MLP weights live in the constant bank: weight reads are warp-uniform,
// so they ride the LDC port instead of burning l1tex wavefronts.
__constant__ float cW1[96 * WIDTH];      // 24 KB   [96][64]
__constant__ float cW2T[WIDTH * WIDTH];  // 16 KB   cW2T[j][k] = W2[k][j]
__constant__ float cW3[WIDTH * 9];       // 2.25 KB [64][9]

__device__ float g_w2t[WIDTH * WIDTH];   // transpose staging

__global__ void transpose_w2(const float* __restrict__ W2) {
    int i = blockIdx.x * 256 + threadIdx.x;
    if (i < WIDTH * WIDTH) {
        int k = i >> 6, j = i & 63;
        g_w2t[j * WIDTH + k] = W2[i];
    }
}

// packed f32x2 fma (Blackwell FFMA2)
__device__ __forceinline__ u64 ffma2(u64 a, u64 b, u64 c) {
    u64 d;
    asm("fma.rn.f32x2 %0, %1, %2, %3;" : "=l"(d) : "l"(a), "l"(b), "l"(c));
    return d;
}
__device__ __forceinline__ u64 dup2(float x) {
    u64 d;
    asm("mov.b64 %0, {%1, %1};" : "=l"(d) : "f"(x));
    return d;
}

// Accumulate one level's (f0, f1) into h1 (32 packed f32x2) with W1 rows
// (row, row+1). Uniform constant-bank reads (LDC), off the l1tex pipe.
__device__ __forceinline__ void acc_l1(int row, float f0, float f1,
                                       u64* __restrict__ hp) {
    u64 F0 = dup2(f0), F1 = dup2(f1);
    const ulonglong2* w0 = (const ulonglong2*)(cW1 + row * WIDTH);
    const ulonglong2* w1 = (const ulonglong2*)(cW1 + (row + 1) * WIDTH);
#pragma unroll
    for (int j = 0; j < 16; j++) {
        ulonglong2 a = w0[j];
        ulonglong2 b = w1[j];
        hp[2 * j + 0] = ffma2(F0, a.x, ffma2(F1, b.x, hp[2 * j + 0]));
        hp[2 * j + 1] = ffma2(F0, a.y, ffma2(F1, b.y, hp[2 * j + 1]));
    }
}

// R3 gather scheme (measured best): if floor(x*r) even, both x-corners sit in
// one aligned float4; else two float2 gathers.
__device__ __forceinline__ void gather_pair(const float2* __restrict__ base,
                                            bool even, uint32_t ax0, uint32_t e,
                                            float vx0, float vx1, float wt,
                                            float& f0, float& f1) {
    if (even) {
        uint32_t id0 = (ax0 ^ e) & HG_TMASK;
        float4 q = __ldg((const float4*)base + (id0 >> 1));
        bool h = (id0 & 1u) != 0u;
        float wl = h ? vx1 : vx0;   // weight on q.xy
        float wh = h ? vx0 : vx1;   // weight on q.zw
        f0 = fmaf(wt, fmaf(wl, q.x, wh * q.z), f0);
        f1 = fmaf(wt, fmaf(wl, q.y, wh * q.w), f1);
    } else {
        float2 u = __ldg(base + ((ax0 ^ e) & HG_TMASK));
        float2 v = __ldg(base + (((ax0 + 1u) ^ e) & HG_TMASK));
        f0 = fmaf(wt, fmaf(vx0, u.x, vx1 * v.x), f0);
        f1 = fmaf(wt, fmaf(vx0, u.y, vx1 * v.y), f1);
    }
}

__device__ __forceinline__ void encode3(float x0, float x1, float x2,
                                        const float* __restrict__ tab,
                                        int kbase, u64* __restrict__ hp) {
#pragma unroll 1
    for (int l = 0; l < HG_L; l++) {
        float r = c_res[l];
        float px = x0 * r, py = x1 * r, pz = x2 * r;
        float fx = floorf(px), fy = floorf(py), fz = floorf(pz);
        float wx = px - fx, wy = py - fy, wz = pz - fz;

        uint32_t ax0 = (uint32_t)fx;
        uint32_t ey[2], ez[2];
        ey[0] = (uint32_t)fy * P1;  ey[1] = ey[0] + P1;
        ez[0] = (uint32_t)fz * P2;  ez[1] = ez[0] + P2;
        float vx0 = 1.f - wx, vx1 = wx;
        float vy[2] = {1.f - wy, wy};
        float vz[2] = {1.f - wz, wz};

        const bool even = (ax0 & 1u) == 0u;
        const float2* base = (const float2*)tab + (size_t)l * HG_T;

        float f0 = 0.f, f1 = 0.f;
#pragma unroll
        for (int c = 0; c < 4; c++) {
            const int by = c >> 1, bz = c & 1;
            gather_pair(base, even, ax0, ey[by] ^ ez[bz],
                        vx0, vx1, vy[by] * vz[bz], f0, f1);
        }
        acc_l1(kbase + 2 * l, f0, f1, hp);
    }
}

__device__ __forceinline__ void encode4(float x0, float x1, float x2, float x3,
                                        const float* __restrict__ tab,
                                        int kbase, u64* __restrict__ hp) {
#pragma unroll 1
    for (int l = 0; l < HG_L; l++) {
        float r = c_res[l];
        float px = x0 * r, py = x1 * r, pz = x2 * r, pw = x3 * r;
        float fx = floorf(px), fy = floorf(py), fz = floorf(pz), fw = floorf(pw);
        float wx = px - fx, wy = py - fy, wz = pz - fz, ww = pw - fw;

        uint32_t ax0 = (uint32_t)fx;
        uint32_t ey[2], ez[2], ew[2];
        ey[0] = (uint32_t)fy * P1;  ey[1] = ey[0] + P1;
        ez[0] = (uint32_t)fz * P2;  ez[1] = ez[0] + P2;
        ew[0] = (uint32_t)fw * P3;  ew[1] = ew[0] + P3;
        float vx0 = 1.f - wx, vx1 = wx;
        float vy[2] = {1.f - wy, wy};
        float vz[2] = {1.f - wz, wz};
        float vw[2] = {1.f - ww, ww};

        const bool even = (ax0 & 1u) == 0u;
        const float2* base = (const float2*)tab + (size_t)l * HG_T;

        float f0 = 0.f, f1 = 0.f;
#pragma unroll
        for (int c = 0; c < 8; c++) {
            const int by = (c >> 2) & 1, bz = (c >> 1) & 1, bw = c & 1;
            gather_pair(base, even, ax0, ey[by] ^ ez[bz] ^ ew[bw],
                        vx0, vx1, vy[by] * (vz[bz] * vw[bw]), f0, f1);
        }
        acc_l1(kbase + 2 * l, f0, f1, hp);
    }
}

__global__ __launch_bounds__(256, 2)
void hashgrid_mlp_kernel(const float* __restrict__ fc,
                         const float* __restrict__ fn,
                         const float* __restrict__ pe,
                         const float* __restrict__ pos_tab,
                         const float* __restrict__ nrm_tab,
                         const float* __restrict__ pose_tab,
                         float* __restrict__ out, int n) {
    const int idx = blockIdx.x * 256 + threadIdx.x;
    if (idx >= n) return;

    u64 hp[32];
#pragma unroll
    for (int j = 0; j < 32; j++) hp[j] = 0ull;

    {
        float x0 = __ldg(fc + (size_t)idx * 3 + 0);
        float x1 = __ldg(fc + (size_t)idx * 3 + 1);
        float x2 = __ldg(fc + (size_t)idx * 3 + 2);
        encode3(x0, x1, x2, pos_tab, 0, hp);
    }
    {
        float x0 = __ldg(fn + (size_t)idx * 3 + 0);
        float x1 = __ldg(fn + (size_t)idx * 3 + 1);
        float x2 = __ldg(fn + (size_t)idx * 3 + 2);
        encode3(x0, x1, x2, nrm_tab, 32, hp);
    }
    {
        float x0 = __ldg(pe + (size_t)idx * 4 + 0);
        float x1 = __ldg(pe + (size_t)idx * 4 + 1);
        float x2 = __ldg(pe + (size_t)idx * 4 + 2);
        float x3 = __ldg(pe + (size_t)idx * 4 + 3);
        encode4(x0, x1, x2, x3, pose_tab, 64, hp);
    }

    // unpack + relu(layer 1)
    float h1[WIDTH];
#pragma unroll
    for (int j = 0; j < 32; j++) {
        float lo, hi;
        asm("mov.b64 {%0, %1}, %2;" : "=f"(lo), "=f"(hi) : "l"(hp[j]));
        h1[2 * j + 0] = fmaxf(lo, 0.f);
        h1[2 * j + 1] = fmaxf(hi, 0.f);
    }

    // layers 2 + 3 streamed; weights via constant port
    float acc[9];
#pragma unroll
    for (int o = 0; o < 9; o++) acc[o] = 0.f;

#pragma unroll 1
    for (int j = 0; j < WIDTH; j++) {
        const float4* wr = (const float4*)(cW2T + j * WIDTH);
        float s0 = 0.f, s1 = 0.f, s2 = 0.f, s3 = 0.f;
#pragma unroll
        for (int k = 0; k < WIDTH / 4; k++) {
            float4 a = wr[k];
            s0 = fmaf(h1[4 * k + 0], a.x, s0);
            s1 = fmaf(h1[4 * k + 1], a.y, s1);
            s2 = fmaf(h1[4 * k + 2], a.z, s2);
            s3 = fmaf(h1[4 * k + 3], a.w, s3);
        }
        float s = fmaxf((s0 + s1) + (s2 + s3), 0.f);
        const float* w3 = cW3 + j * 9;
#pragma unroll
        for (int o = 0; o < 9; o++) acc[o] = fmaf(s, w3[o], acc[o]);
    }

    float* op = out + (size_t)idx * 9;
#pragma unroll
    for (int o = 0; o < 9; o++) op[o] = acc[o];
}

extern "C" void kernel_launch(void* const* d_in, const int* in_sizes, int n_in,
                              void* d_out, int out_size) {
    const float* fc = (const float*)d_in[0];
    const float* fn = (const float*)d_in[1];
    const float* pe = (const float*)d_in[2];
    const float* pt = (const float*)d_in[3];
    const float* nt = (const float*)d_in[4];
    const float* qt = (const float*)d_in[5];
    const float* W1 = (const float*)d_in[6];
    const float* W2 = (const float*)d_in[7];
    const float* W3 = (const float*)d_in[8];
    float* out = (float*)d_out;

    const int n = in_sizes[0] / 3;

    // Stage weights into the constant bank (all D2D, graph-capturable).
    transpose_w2<<<(WIDTH * WIDTH + 255) / 256, 256>>>(W2);
    cudaMemcpyToSymbolAsync(cW1, W1, 96 * WIDTH * sizeof(float), 0,
                            cudaMemcpyDeviceToDevice, 0);
    void* w2t_dev = nullptr;
    cudaGetSymbolAddress(&w2t_dev, g_w2t);
    cudaMemcpyToSymbolAsync(cW2T, w2t_dev, WIDTH * WIDTH * sizeof(float), 0,
                            cudaMemcpyDeviceToDevice, 0);
    cudaMemcpyToSymbolAsync(cW3, W3, WIDTH * 9 * sizeof(float), 0,
                            cudaMemcpyDeviceToDevice, 0);

    const int blocks = (n + 255) / 256;
    hashgrid_mlp_kernel<<<blocks, 256>>>(fc, fn, pe, pt, nt, qt, out, n);
}